// round 15
// baseline (speedup 1.0000x reference)
#include <cuda_runtime.h>
#include <cuda_fp16.h>
#include <math.h>
#include <float.h>

// Problem constants
#define NT   16
#define NN   8
#define NF   6
#define TILE 334
#define AA   21
#define KK   20
#define UU   600
#define LL   315               // TILE - KK + 1
#define NSEQ (NT*NN*NF)        // 768
#define UPAD 640               // padded U for the fp16 table (5 * 128)
#define UC   128               // u-chunk per work item
#define NCH  5                 // UPAD / UC
#define NITEMS (NCH*NSEQ)      // 3840 work items (uc-major: item = uc*768+seq)
#define NCHUNK (128*NCH)       // 640 (grp,uc) S-chunks; chunk = item/6
#define GRID 148               // persistent CTAs (1 per SM, 1024 threads)
#define NTHR 1024
#define MAXLOC 27              // max items per CTA (ceil(3840/148)=26) + 1

#define S_ELEMS (NT*NN*UU)             // 76800
#define R_ELEMS (KK*AA*UU)             // 252000
#define Z_ELEMS (NSEQ*LL*UU)           // 145152000

// Shared memory layout (table relaid as [c][k][u])
#define SM_TBL_BYTES (AA*KK*UC*2)      // 107520
#define SM_IDS_OFF   SM_TBL_BYTES
#define IDS_STRIDE   344               // padded per-seq byte stride
#define SM_TOTAL     (SM_IDS_OFF + MAXLOC*IDS_STRIDE)  // 116808 (<227KB)

// Device scratch (static: no allocations allowed)
__device__ __align__(16) unsigned char g_ids[NSEQ * TILE];
__device__ __align__(16) __half        g_Rh[KK * AA * UPAD];
__device__ __align__(16) int           g_Sint[S_ELEMS];
__device__                int          g_ccnt[NCHUNK];   // per-chunk owner counters

// float <-> monotonic int key (atomicMax on possibly-negative floats)
__device__ __forceinline__ int fenc(float f) {
    int i = __float_as_int(f);
    return (i >= 0) ? i : (i ^ 0x7FFFFFFF);
}
__device__ __forceinline__ float fdec(int k) {
    return __int_as_float((k >= 0) ? k : (k ^ 0x7FFFFFFF));
}

// owner CTA of item s under the start=(g*NITEMS)/GRID partition
__device__ __forceinline__ int owner_of(int s) {
    return ((s + 1) * GRID - 1) / NITEMS;
}

// ---------------------------------------------------------------------------
// Kernel 1 (fused prep): decode one-hot X -> byte ids (4x uint4 per thread)
//   + R = log(max(P/Q,eps)) -> fp32 out + fp16 table
//   + g_Sint / g_ccnt init (every launch -> graph-replay safe).
// ---------------------------------------------------------------------------
#define XFLOATS (NSEQ * TILE * AA)     // 5,386,752 (divisible by 16)
#define PREP_THREADS (XFLOATS / 16)    // 336,672
__global__ void prep_kernel(const uint4* __restrict__ X4,
                            const float* __restrict__ P,
                            const float* __restrict__ Q,
                            float* __restrict__ Rout) {
    int i = blockIdx.x * blockDim.x + threadIdx.x;

    if (i < XFLOATS / 16) {            // --- decode (4x uint4 for MLP) ---
        uint4 v0 = X4[4 * i];
        uint4 v1 = X4[4 * i + 1];
        uint4 v2 = X4[4 * i + 2];
        uint4 v3 = X4[4 * i + 3];
        int b0 = i * 16;
        if (v0.x) { int e = b0;      g_ids[e / AA] = (unsigned char)(e % AA); }
        if (v0.y) { int e = b0 + 1;  g_ids[e / AA] = (unsigned char)(e % AA); }
        if (v0.z) { int e = b0 + 2;  g_ids[e / AA] = (unsigned char)(e % AA); }
        if (v0.w) { int e = b0 + 3;  g_ids[e / AA] = (unsigned char)(e % AA); }
        if (v1.x) { int e = b0 + 4;  g_ids[e / AA] = (unsigned char)(e % AA); }
        if (v1.y) { int e = b0 + 5;  g_ids[e / AA] = (unsigned char)(e % AA); }
        if (v1.z) { int e = b0 + 6;  g_ids[e / AA] = (unsigned char)(e % AA); }
        if (v1.w) { int e = b0 + 7;  g_ids[e / AA] = (unsigned char)(e % AA); }
        if (v2.x) { int e = b0 + 8;  g_ids[e / AA] = (unsigned char)(e % AA); }
        if (v2.y) { int e = b0 + 9;  g_ids[e / AA] = (unsigned char)(e % AA); }
        if (v2.z) { int e = b0 + 10; g_ids[e / AA] = (unsigned char)(e % AA); }
        if (v2.w) { int e = b0 + 11; g_ids[e / AA] = (unsigned char)(e % AA); }
        if (v3.x) { int e = b0 + 12; g_ids[e / AA] = (unsigned char)(e % AA); }
        if (v3.y) { int e = b0 + 13; g_ids[e / AA] = (unsigned char)(e % AA); }
        if (v3.z) { int e = b0 + 14; g_ids[e / AA] = (unsigned char)(e % AA); }
        if (v3.w) { int e = b0 + 15; g_ids[e / AA] = (unsigned char)(e % AA); }
    }

    if (i < S_ELEMS) g_Sint[i] = 0x80000000;   // --- S init (-inf key) ---
    if (i < NCHUNK)  g_ccnt[i] = 0;            // --- chunk counters ---

    if (i < KK * AA * UPAD) {          // --- R / fp16 table ---
        int u  = i % UPAD;
        int ka = i / UPAD;
        int a  = ka % AA;
        if (u < UU) {
            float p = P[ka * UU + u];
            float r = logf(fmaxf(p / Q[a], 1e-6f));
            g_Rh[i] = __float2half(r);
            if (Rout) Rout[ka * UU + u] = r;
        } else {
            g_Rh[i] = __float2half(0.0f);
        }
    }
}

// ---------------------------------------------------------------------------
// Kernel 2: persistent main gather-sum, sync-free steady state.
//   148 persistent CTAs (1/SM, 1024 threads = 32 warps). Items uc-major;
//   ids staged once, table staged <=2x per CTA (the only block syncs).
//   S: per-warp reg max -> atomicMax(g_Sint); at CTA exit, a last-owner
//   protocol (per-chunk counters, one fence per thread) decodes finished
//   (grp,uc) chunks directly into S — no separate writeS kernel.
//   warp = 2 l-positions (16 lanes each); lane covers 8 u (fp16x8).
// ---------------------------------------------------------------------------
__global__ void __launch_bounds__(NTHR, 1)
profile_main(float* __restrict__ Z, float* __restrict__ S) {
    extern __shared__ unsigned char sm[];
    __half*        tbl  = (__half*)sm;
    unsigned char* idsm = sm + SM_IDS_OFF;
    __shared__ int s_marked[16];
    __shared__ int s_nmark;

    const int tid    = threadIdx.x;
    const int lane   = tid & 31;
    const int wid    = tid >> 5;           // 0..31
    const int lane16 = lane & 15;
    const int hf     = lane >> 4;          // which l within the warp
    const __half* tlane = tbl + lane16 * 8;
    const half2 hz = __half2half2(__float2half(0.0f));
    const int needS = (S != nullptr);

    const int start = (blockIdx.x * NITEMS) / GRID;
    const int end   = ((blockIdx.x + 1) * NITEMS) / GRID;
    const int nloc  = end - start;

    // --- stage ids for ALL this CTA's items once (first table sync covers) ---
    for (int i = tid; i < nloc * IDS_STRIDE; i += NTHR) {
        int slot = i / IDS_STRIDE, p = i % IDS_STRIDE;
        int b = (start + slot) % NSEQ;
        unsigned v = 0;
        if (p < TILE) v = g_ids[b * TILE + p];
        idsm[i] = (unsigned char)v;
    }

    int cur_uc  = -1;
    int cur_grp = -1;
    int u0 = 0;
    bool uval = true;

    float rmax[8];
#pragma unroll
    for (int i = 0; i < 8; ++i) rmax[i] = -FLT_MAX;

    // flush rmax -> global atomicMax for (cur_grp, u0); resets rmax
    auto flushS = [&](void) {
#pragma unroll
        for (int i = 0; i < 8; ++i) {
            float v = rmax[i];
            v = fmaxf(v, __shfl_xor_sync(0xFFFFFFFFu, v, 16));
            if (hf == 0) {
                int ucol = u0 + lane16 * 8 + i;
                if (ucol < UU)
                    atomicMax(&g_Sint[cur_grp * UU + ucol], fenc(v));
            }
            rmax[i] = -FLT_MAX;
        }
    };

    for (int item = start; item < end; ++item) {
        const int uc  = item / NSEQ;
        const int b   = item % NSEQ;
        const int grp = b / NF;
        const int slot = item - start;

        if (uc != cur_uc) {
            if (needS && cur_grp >= 0) flushS();
            cur_grp = -1;
            __syncthreads();   // all warps done reading old table (also orders ids)
            const uint4* src = (const uint4*)g_Rh;      // row stride UPAD/8 = 80
            uint4*       dst = (uint4*)tbl;             // row stride UC/8   = 16
            for (int i = tid; i < AA * KK * 16; i += NTHR) {
                int row = i >> 4, col = i & 15;         // row = a*20 + k
                int a = row / KK, k = row - a * KK;
                dst[i] = src[(k * AA + a) * (UPAD / 8) + uc * 16 + col];
            }
            __syncthreads();
            cur_uc = uc;
            u0 = uc * UC;
            uval = (u0 + lane16 * 8) < UU;
        }
        if (grp != cur_grp) {
            if (needS && cur_grp >= 0) flushS();
            cur_grp = grp;
        }

        const unsigned* idw = (const unsigned*)(idsm + slot * IDS_STRIDE);

#pragma unroll 1
        for (int it = 0; it < 5; ++it) {
            const int l  = it * 64 + wid * 2 + hf;       // 0..319
            if (l >= LL + 1) continue;     // whole-warp skip (wid>=30 @ it==4);
                                           // only l==315 (wid29/hf1) stays clamped
            const int lc = (l < LL) ? l : (LL - 1);      // clamp (dup benign)
            const bool lv = (l < LL);

            // Register window of 24 aligned seq bytes covering s[lc..lc+20]
            const int wb = lc >> 2;
            const int sh = (lc & 3) * 8;
            unsigned w[7];
#pragma unroll
            for (int i = 0; i < 7; ++i) w[i] = idw[wb + i];
            unsigned aw[6];
#pragma unroll
            for (int i = 0; i < 6; ++i) aw[i] = __funnelshift_r(w[i], w[i + 1], sh);

            // 4-way split fp16 accumulation over k (j = k&3)
            half2 acc[4][4];
#pragma unroll
            for (int j = 0; j < 4; ++j)
#pragma unroll
                for (int q = 0; q < 4; ++q) acc[j][q] = hz;

#pragma unroll
            for (int k = 0; k < KK; ++k) {
                unsigned c = __byte_perm(aw[k >> 2], 0u, 0x4440u | (k & 3));
                const uint4* p = (const uint4*)(tlane + c * (KK * UC) + k * UC);
                uint4 v0 = *p;          // 8 halves = lane's 8 u values
                const int j = k & 3;
                acc[j][0] = __hadd2(acc[j][0], *reinterpret_cast<half2*>(&v0.x));
                acc[j][1] = __hadd2(acc[j][1], *reinterpret_cast<half2*>(&v0.y));
                acc[j][2] = __hadd2(acc[j][2], *reinterpret_cast<half2*>(&v0.z));
                acc[j][3] = __hadd2(acc[j][3], *reinterpret_cast<half2*>(&v0.w));
            }

            // combine: (acc0+acc1), (acc2+acc3) in fp16, final sum in fp32
            float out[8];
#pragma unroll
            for (int q = 0; q < 4; ++q) {
                half2 A  = __hadd2(acc[0][q], acc[1][q]);
                half2 B  = __hadd2(acc[2][q], acc[3][q]);
                float2 fa = __half22float2(A);
                float2 fb = __half22float2(B);
                out[2 * q]     = fa.x + fb.x;
                out[2 * q + 1] = fa.y + fb.y;
            }
#pragma unroll
            for (int i = 0; i < 8; ++i) rmax[i] = fmaxf(rmax[i], out[i]);

            if (Z != nullptr && lv && uval) {
                size_t zi = ((size_t)b * LL + l) * UU + (size_t)(u0 + lane16 * 8);
                *(float4*)(Z + zi)     = make_float4(out[0], out[1], out[2], out[3]);
                *(float4*)(Z + zi + 4) = make_float4(out[4], out[5], out[6], out[7]);
            }
        }
    }

    if (needS) {
        if (cur_grp >= 0) flushS();
        __threadfence();          // each thread orders ALL its atomicMax ops
        __syncthreads();          // every warp has fenced
        if (tid == 0) {
            int n = 0;
            const int cfirst = start / NF;          // chunk = item/6
            const int clast  = (end - 1) / NF;
            for (int c = cfirst; c <= clast; ++c) {
                int s0 = c * NF;
                int expected = owner_of(s0 + NF - 1) - owner_of(s0) + 1;
                if (atomicAdd(&g_ccnt[c], 1) == expected - 1)
                    s_marked[n++] = c;              // we are the last owner
            }
            s_nmark = n;
        }
        __syncthreads();
        __threadfence();          // acquire: contributions visible before reads
        const int n = s_nmark;
        if (wid < n) {            // warp w decodes marked chunk w (128 values)
            int c = s_marked[wid];
            int grp2 = c & 127, uc2 = c >> 7;
#pragma unroll
            for (int q = 0; q < 4; ++q) {
                int ucol = uc2 * UC + lane * 4 + q;
                if (ucol < UU) {
                    int idx = grp2 * UU + ucol;
                    S[idx] = fdec(g_Sint[idx]);
                }
            }
        }
    }
}

// ---------------------------------------------------------------------------
extern "C" void kernel_launch(void* const* d_in, const int* in_sizes, int n_in,
                              void* d_out, int out_size) {
    const float* X = (const float*)d_in[0];
    const float* P = (const float*)d_in[1];
    const float* Q = (const float*)d_in[2];
    float* out = (float*)d_out;

    // Resolve output layout from out_size (reference returns (S, R, Z)).
    float *Sp = nullptr, *Rp = nullptr, *Zp = nullptr;
    if (out_size == S_ELEMS + R_ELEMS + Z_ELEMS) {
        Sp = out; Rp = out + S_ELEMS; Zp = out + S_ELEMS + R_ELEMS;
    } else if (out_size == S_ELEMS) {
        Sp = out;
    } else if (out_size == R_ELEMS) {
        Rp = out;
    } else if (out_size == Z_ELEMS) {
        Zp = out;
    } else if (out_size == S_ELEMS + R_ELEMS) {
        Sp = out; Rp = out + S_ELEMS;
    } else if (out_size == S_ELEMS + Z_ELEMS) {
        Sp = out; Zp = out + S_ELEMS;
    } else if (out_size == R_ELEMS + Z_ELEMS) {
        Rp = out; Zp = out + R_ELEMS;
    } else {
        Sp = out; Rp = out + S_ELEMS; Zp = out + S_ELEMS + R_ELEMS;
    }

    cudaFuncSetAttribute(profile_main,
                         cudaFuncAttributeMaxDynamicSharedMemorySize, SM_TOTAL);

    prep_kernel<<<(PREP_THREADS + 255) / 256, 256>>>((const uint4*)X, P, Q, Rp);
    profile_main<<<GRID, NTHR, SM_TOTAL>>>(Zp, Sp);
}

// round 16
// speedup vs baseline: 1.0372x; 1.0372x over previous
#include <cuda_runtime.h>
#include <cuda_fp16.h>
#include <math.h>
#include <float.h>

// Problem constants
#define NT   16
#define NN   8
#define NF   6
#define TILE 334
#define AA   21
#define KK   20
#define UU   600
#define LL   315               // TILE - KK + 1
#define NSEQ (NT*NN*NF)        // 768
#define UPAD 640               // padded U for the fp16 table (5 * 128)
#define UC   128               // u-chunk per work item
#define NCH  5                 // UPAD / UC
#define NITEMS (NCH*NSEQ)      // 3840 work items (uc-major: item = uc*768+seq)
#define GRID 148               // persistent CTAs (1 per SM, 1024 threads)
#define NTHR 1024
#define MAXLOC 27              // max items per CTA (ceil(3840/148)=26) + 1

#define S_ELEMS (NT*NN*UU)             // 76800
#define R_ELEMS (KK*AA*UU)             // 252000
#define Z_ELEMS (NSEQ*LL*UU)           // 145152000

// Shared memory layout (table relaid as [c][k][u])
#define SM_TBL_BYTES (AA*KK*UC*2)      // 107520
#define SM_IDS_OFF   SM_TBL_BYTES
#define IDS_STRIDE   344               // padded per-seq byte stride
#define SM_TOTAL     (SM_IDS_OFF + MAXLOC*IDS_STRIDE)  // 116808 (<227KB)

// Device scratch (static: no allocations allowed)
__device__ __align__(16) unsigned char g_ids[NSEQ * TILE];
__device__ __align__(16) __half        g_Rh[KK * AA * UPAD];
__device__ __align__(16) int           g_Sint[S_ELEMS];

// float <-> monotonic int key (atomicMax on possibly-negative floats)
__device__ __forceinline__ int fenc(float f) {
    int i = __float_as_int(f);
    return (i >= 0) ? i : (i ^ 0x7FFFFFFF);
}
__device__ __forceinline__ float fdec(int k) {
    return __int_as_float((k >= 0) ? k : (k ^ 0x7FFFFFFF));
}

// ---------------------------------------------------------------------------
// Kernel 1 (fused prep): decode one-hot X -> byte ids (2x uint4 per thread;
//   measured faster than 4x in R12/R14 A/B)
//   + R = log(max(P/Q,eps)) -> fp32 out + fp16 table
//   + g_Sint init (every launch -> graph-replay safe).
// ---------------------------------------------------------------------------
#define XFLOATS (NSEQ * TILE * AA)     // 5,386,752 (divisible by 8)
#define PREP_THREADS (XFLOATS / 8)     // 673,344
__global__ void prep_kernel(const uint4* __restrict__ X4,
                            const float* __restrict__ P,
                            const float* __restrict__ Q,
                            float* __restrict__ Rout) {
    int i = blockIdx.x * blockDim.x + threadIdx.x;

    if (i < XFLOATS / 8) {             // --- decode (2x uint4 for MLP) ---
        uint4 v0 = X4[2 * i];
        uint4 v1 = X4[2 * i + 1];
        int b0 = i * 8;
        if (v0.x) { int e = b0;     g_ids[e / AA] = (unsigned char)(e % AA); }
        if (v0.y) { int e = b0 + 1; g_ids[e / AA] = (unsigned char)(e % AA); }
        if (v0.z) { int e = b0 + 2; g_ids[e / AA] = (unsigned char)(e % AA); }
        if (v0.w) { int e = b0 + 3; g_ids[e / AA] = (unsigned char)(e % AA); }
        if (v1.x) { int e = b0 + 4; g_ids[e / AA] = (unsigned char)(e % AA); }
        if (v1.y) { int e = b0 + 5; g_ids[e / AA] = (unsigned char)(e % AA); }
        if (v1.z) { int e = b0 + 6; g_ids[e / AA] = (unsigned char)(e % AA); }
        if (v1.w) { int e = b0 + 7; g_ids[e / AA] = (unsigned char)(e % AA); }
    }

    if (i < S_ELEMS) g_Sint[i] = 0x80000000;   // --- S init (-inf key) ---

    if (i < KK * AA * UPAD) {          // --- R / fp16 table ---
        int u  = i % UPAD;
        int ka = i / UPAD;
        int a  = ka % AA;
        if (u < UU) {
            float p = P[ka * UU + u];
            float r = logf(fmaxf(p / Q[a], 1e-6f));
            g_Rh[i] = __float2half(r);
            if (Rout) Rout[ka * UU + u] = r;
        } else {
            g_Rh[i] = __float2half(0.0f);
        }
    }
}

// Kernel 3: g_Sint -> S
__global__ void writeS_kernel(float* __restrict__ S) {
    int i = blockIdx.x * blockDim.x + threadIdx.x;
    if (i < S_ELEMS) S[i] = fdec(g_Sint[i]);
}

// ---------------------------------------------------------------------------
// Kernel 2: persistent main gather-sum, sync-free steady state.
//   148 persistent CTAs (1/SM, 1024 threads = 32 warps). Items uc-major;
//   ids staged once, table staged <=2x per CTA (the only block syncs).
//   S kept in regs, flushed to global atomicMax on (grp|uc) change.
//   warp = 2 l-positions (16 lanes each); lane covers 8 u (fp16x8).
//   Table [c][k][u]: per-k address = c*5120B + k*256B (immediate); each
//   LDS.128 8-lane phase reads 128B contiguous -> conflict-free.
//   Z stores are evict-first streaming (__stcs): the 580MB Z stream should
//   not occupy L2 against table/ids reads. (Only change vs R14 body.)
// ---------------------------------------------------------------------------
__global__ void __launch_bounds__(NTHR, 1)
profile_main(float* __restrict__ Z, int needS) {
    extern __shared__ unsigned char sm[];
    __half*        tbl  = (__half*)sm;
    unsigned char* idsm = sm + SM_IDS_OFF;

    const int tid    = threadIdx.x;
    const int lane   = tid & 31;
    const int wid    = tid >> 5;           // 0..31
    const int lane16 = lane & 15;
    const int hf     = lane >> 4;          // which l within the warp
    const __half* tlane = tbl + lane16 * 8;
    const half2 hz = __half2half2(__float2half(0.0f));

    const int start = (blockIdx.x * NITEMS) / GRID;
    const int end   = ((blockIdx.x + 1) * NITEMS) / GRID;
    const int nloc  = end - start;

    // --- stage ids for ALL this CTA's items once (first table sync covers) ---
    for (int i = tid; i < nloc * IDS_STRIDE; i += NTHR) {
        int slot = i / IDS_STRIDE, p = i % IDS_STRIDE;
        int b = (start + slot) % NSEQ;
        unsigned v = 0;
        if (p < TILE) v = g_ids[b * TILE + p];
        idsm[i] = (unsigned char)v;
    }

    int cur_uc  = -1;
    int cur_grp = -1;
    int u0 = 0;
    bool uval = true;

    float rmax[8];
#pragma unroll
    for (int i = 0; i < 8; ++i) rmax[i] = -FLT_MAX;

    // flush rmax -> global atomicMax for (cur_grp, u0); resets rmax
    auto flushS = [&](void) {
#pragma unroll
        for (int i = 0; i < 8; ++i) {
            float v = rmax[i];
            v = fmaxf(v, __shfl_xor_sync(0xFFFFFFFFu, v, 16));
            if (hf == 0) {
                int ucol = u0 + lane16 * 8 + i;
                if (ucol < UU)
                    atomicMax(&g_Sint[cur_grp * UU + ucol], fenc(v));
            }
            rmax[i] = -FLT_MAX;
        }
    };

    for (int item = start; item < end; ++item) {
        const int uc  = item / NSEQ;
        const int b   = item % NSEQ;
        const int grp = b / NF;
        const int slot = item - start;

        if (uc != cur_uc) {
            if (needS && cur_grp >= 0) flushS();
            cur_grp = -1;
            __syncthreads();   // all warps done reading old table (also orders ids)
            const uint4* src = (const uint4*)g_Rh;      // row stride UPAD/8 = 80
            uint4*       dst = (uint4*)tbl;             // row stride UC/8   = 16
            for (int i = tid; i < AA * KK * 16; i += NTHR) {
                int row = i >> 4, col = i & 15;         // row = a*20 + k
                int a = row / KK, k = row - a * KK;
                dst[i] = src[(k * AA + a) * (UPAD / 8) + uc * 16 + col];
            }
            __syncthreads();
            cur_uc = uc;
            u0 = uc * UC;
            uval = (u0 + lane16 * 8) < UU;
        }
        if (grp != cur_grp) {
            if (needS && cur_grp >= 0) flushS();
            cur_grp = grp;
        }

        const unsigned* idw = (const unsigned*)(idsm + slot * IDS_STRIDE);

#pragma unroll 1
        for (int it = 0; it < 5; ++it) {
            const int l  = it * 64 + wid * 2 + hf;       // 0..319
            if (l >= LL + 1) continue;     // whole-warp skip (wid>=30 @ it==4);
                                           // only l==315 (wid29/hf1) stays clamped
            const int lc = (l < LL) ? l : (LL - 1);      // clamp (dup benign)
            const bool lv = (l < LL);

            // Register window of 24 aligned seq bytes covering s[lc..lc+20]
            const int wb = lc >> 2;
            const int sh = (lc & 3) * 8;
            unsigned w[7];
#pragma unroll
            for (int i = 0; i < 7; ++i) w[i] = idw[wb + i];
            unsigned aw[6];
#pragma unroll
            for (int i = 0; i < 6; ++i) aw[i] = __funnelshift_r(w[i], w[i + 1], sh);

            // 4-way split fp16 accumulation over k (j = k&3)
            half2 acc[4][4];
#pragma unroll
            for (int j = 0; j < 4; ++j)
#pragma unroll
                for (int q = 0; q < 4; ++q) acc[j][q] = hz;

#pragma unroll
            for (int k = 0; k < KK; ++k) {
                unsigned c = __byte_perm(aw[k >> 2], 0u, 0x4440u | (k & 3));
                const uint4* p = (const uint4*)(tlane + c * (KK * UC) + k * UC);
                uint4 v0 = *p;          // 8 halves = lane's 8 u values
                const int j = k & 3;
                acc[j][0] = __hadd2(acc[j][0], *reinterpret_cast<half2*>(&v0.x));
                acc[j][1] = __hadd2(acc[j][1], *reinterpret_cast<half2*>(&v0.y));
                acc[j][2] = __hadd2(acc[j][2], *reinterpret_cast<half2*>(&v0.z));
                acc[j][3] = __hadd2(acc[j][3], *reinterpret_cast<half2*>(&v0.w));
            }

            // combine: (acc0+acc1), (acc2+acc3) in fp16, final sum in fp32
            float out[8];
#pragma unroll
            for (int q = 0; q < 4; ++q) {
                half2 A  = __hadd2(acc[0][q], acc[1][q]);
                half2 B  = __hadd2(acc[2][q], acc[3][q]);
                float2 fa = __half22float2(A);
                float2 fb = __half22float2(B);
                out[2 * q]     = fa.x + fb.x;
                out[2 * q + 1] = fa.y + fb.y;
            }
#pragma unroll
            for (int i = 0; i < 8; ++i) rmax[i] = fmaxf(rmax[i], out[i]);

            if (Z != nullptr && lv && uval) {
                size_t zi = ((size_t)b * LL + l) * UU + (size_t)(u0 + lane16 * 8);
                __stcs((float4*)(Z + zi),
                       make_float4(out[0], out[1], out[2], out[3]));
                __stcs((float4*)(Z + zi + 4),
                       make_float4(out[4], out[5], out[6], out[7]));
            }
        }
    }

    if (needS && cur_grp >= 0) flushS();
}

// ---------------------------------------------------------------------------
extern "C" void kernel_launch(void* const* d_in, const int* in_sizes, int n_in,
                              void* d_out, int out_size) {
    const float* X = (const float*)d_in[0];
    const float* P = (const float*)d_in[1];
    const float* Q = (const float*)d_in[2];
    float* out = (float*)d_out;

    // Resolve output layout from out_size (reference returns (S, R, Z)).
    float *Sp = nullptr, *Rp = nullptr, *Zp = nullptr;
    if (out_size == S_ELEMS + R_ELEMS + Z_ELEMS) {
        Sp = out; Rp = out + S_ELEMS; Zp = out + S_ELEMS + R_ELEMS;
    } else if (out_size == S_ELEMS) {
        Sp = out;
    } else if (out_size == R_ELEMS) {
        Rp = out;
    } else if (out_size == Z_ELEMS) {
        Zp = out;
    } else if (out_size == S_ELEMS + R_ELEMS) {
        Sp = out; Rp = out + S_ELEMS;
    } else if (out_size == S_ELEMS + Z_ELEMS) {
        Sp = out; Zp = out + S_ELEMS;
    } else if (out_size == R_ELEMS + Z_ELEMS) {
        Rp = out; Zp = out + R_ELEMS;
    } else {
        Sp = out; Rp = out + S_ELEMS; Zp = out + S_ELEMS + R_ELEMS;
    }

    cudaFuncSetAttribute(profile_main,
                         cudaFuncAttributeMaxDynamicSharedMemorySize, SM_TOTAL);

    prep_kernel<<<(PREP_THREADS + 255) / 256, 256>>>((const uint4*)X, P, Q, Rp);
    profile_main<<<GRID, NTHR, SM_TOTAL>>>(Zp, Sp != nullptr);
    if (Sp) writeS_kernel<<<(S_ELEMS + 255) / 256, 256>>>(Sp);
}